// round 2
// baseline (speedup 1.0000x reference)
#include <cuda_runtime.h>
#include <math.h>

#define NN 50000
#define EE 600000
#define D  128

// ---------------- device scratch (static: no allocation allowed) -------------
__device__ float  g_buf0[NN * D];
__device__ float  g_buf1[NN * D];
__device__ float  g_A [NN * D];   // lin1(x) (+b1)
__device__ float  g_Bt[NN * D];   // lin2(x) (no bias)
__device__ float  g_Cb[NN * D];   // lin3(x) (+b3)
__device__ float  g_wsum[NN];
__device__ int    g_deg[NN];
__device__ int    g_fill[NN];
__device__ int    g_rowstart[NN + 1];
__device__ int    g_csr_src[EE];
__device__ float  g_csr_w[EE];
__device__ double g_sumd[D];
__device__ double g_sumsqd[D];
__device__ float  g_mean[D];
__device__ float  g_invs[D];
__device__ float  g_A1[NN];
__device__ float  g_base1[NN];

// ---------------- setup kernels ---------------------------------------------
__global__ void zero_kernel() {
    int i = blockIdx.x * blockDim.x + threadIdx.x;
    if (i < D) { g_sumd[i] = 0.0; g_sumsqd[i] = 0.0; }
    if (i < NN) { g_wsum[i] = 0.f; g_deg[i] = 0; g_fill[i] = 0; }
}

// column sums over nodes (double accumulation for exact-ish standardization)
__global__ void colstats_kernel(const float* __restrict__ x) {
    int c = threadIdx.x;               // 0..127
    double s = 0.0, sq = 0.0;
    for (int r = blockIdx.x; r < NN; r += gridDim.x) {
        float v = x[r * D + c];
        s  += (double)v;
        sq += (double)v * (double)v;
    }
    atomicAdd(&g_sumd[c], s);
    atomicAdd(&g_sumsqd[c], sq);
}

__global__ void finalize_stats_kernel() {
    int c = threadIdx.x;
    if (c >= D) return;
    double s = g_sumd[c], sq = g_sumsqd[c];
    double mean = s / (double)NN;
    double var  = (sq - s * s / (double)NN) / (double)(NN - 1);  // ddof=1
    if (var < 0.0) var = 0.0;
    g_mean[c] = (float)mean;
    g_invs[c] = (float)(1.0 / (sqrt(var) + 1e-6));
}

__global__ void normalize_kernel(const float* __restrict__ x) {
    int i = blockIdx.x * blockDim.x + threadIdx.x;   // over NN*32 float4s
    if (i >= NN * 32) return;
    int cg = (i & 31) * 4;
    float4 v = ((const float4*)x)[i];
    v.x = (v.x - g_mean[cg + 0]) * g_invs[cg + 0];
    v.y = (v.y - g_mean[cg + 1]) * g_invs[cg + 1];
    v.z = (v.z - g_mean[cg + 2]) * g_invs[cg + 2];
    v.w = (v.w - g_mean[cg + 3]) * g_invs[cg + 3];
    ((float4*)g_buf0)[i] = v;
}

__global__ void deg_wsum_kernel(const int* __restrict__ ei, const float* __restrict__ ew) {
    int e = blockIdx.x * blockDim.x + threadIdx.x;
    if (e >= EE) return;
    int dst = ei[EE + e];
    atomicAdd(&g_wsum[dst], ew[e]);
    atomicAdd(&g_deg[dst], 1);
}

// single-block exclusive scan of g_deg -> g_rowstart
__global__ void scan_kernel() {
    __shared__ int sh[1024];
    __shared__ int carry;
    int tid = threadIdx.x;
    if (tid == 0) carry = 0;
    __syncthreads();
    for (int base = 0; base < NN; base += 1024) {
        int i = base + tid;
        int v = (i < NN) ? g_deg[i] : 0;
        sh[tid] = v;
        __syncthreads();
        for (int off = 1; off < 1024; off <<= 1) {
            int t = (tid >= off) ? sh[tid - off] : 0;
            __syncthreads();
            sh[tid] += t;
            __syncthreads();
        }
        if (i < NN) g_rowstart[i] = carry + sh[tid] - v;  // exclusive
        __syncthreads();
        if (tid == 1023) carry += sh[1023];
        __syncthreads();
    }
    if (tid == 0) g_rowstart[NN] = EE;
}

__global__ void fill_csr_kernel(const int* __restrict__ ei, const float* __restrict__ ew) {
    int e = blockIdx.x * blockDim.x + threadIdx.x;
    if (e >= EE) return;
    int dst = ei[EE + e];
    int p = g_rowstart[dst] + atomicAdd(&g_fill[dst], 1);
    g_csr_src[p] = ei[e];
    g_csr_w[p]   = ew[e];
}

// ---------------- SGEMM: out[M,128] = X[M,128] @ W[128,128] (+bias) ---------
__global__ void __launch_bounds__(256) sgemm_kernel(
    const float* __restrict__ X, const float* __restrict__ W,
    const float* __restrict__ bias, float* __restrict__ out)
{
    __shared__ float As[8][128];
    __shared__ float Bs[8][128];
    int tid = threadIdx.x;
    int block_row = blockIdx.x * 128;
    int tm = (tid >> 4) * 8;
    int tn = (tid & 15) * 8;
    float acc[8][8] = {};

    int lr = tid >> 1;            // X-tile row 0..127
    int lc = (tid & 1) * 4;       // X-tile col group (0 or 4)
    int wr = tid >> 5;            // W-tile k row 0..7
    int wc = (tid & 31) * 4;      // W-tile col 0..124

    for (int k0 = 0; k0 < 128; k0 += 8) {
        float4 xv = make_float4(0.f, 0.f, 0.f, 0.f);
        int grow = block_row + lr;
        if (grow < NN) xv = *(const float4*)(X + grow * D + k0 + lc);
        As[lc + 0][lr] = xv.x; As[lc + 1][lr] = xv.y;
        As[lc + 2][lr] = xv.z; As[lc + 3][lr] = xv.w;
        *(float4*)&Bs[wr][wc] = *(const float4*)(W + (k0 + wr) * D + wc);
        __syncthreads();
#pragma unroll
        for (int k = 0; k < 8; ++k) {
            float ra[8], rb[8];
#pragma unroll
            for (int i = 0; i < 8; i++) ra[i] = As[k][tm + i];
#pragma unroll
            for (int j = 0; j < 8; j++) rb[j] = Bs[k][tn + j];
#pragma unroll
            for (int i = 0; i < 8; i++)
#pragma unroll
                for (int j = 0; j < 8; j++) acc[i][j] += ra[i] * rb[j];
        }
        __syncthreads();
    }
#pragma unroll
    for (int i = 0; i < 8; i++) {
        int grow = block_row + tm + i;
        if (grow >= NN) break;
#pragma unroll
        for (int j = 0; j < 8; j += 4) {
            float4 v = make_float4(acc[i][j], acc[i][j+1], acc[i][j+2], acc[i][j+3]);
            if (bias) {
                v.x += bias[tn + j];     v.y += bias[tn + j + 1];
                v.z += bias[tn + j + 2]; v.w += bias[tn + j + 3];
            }
            *(float4*)(out + grow * D + tn + j) = v;
        }
    }
}

// ---------------- per-node aggregation + LEConv epilogue + LN + leaky -------
__global__ void __launch_bounds__(256) agg_ln_kernel(
    const float* __restrict__ gamma, const float* __restrict__ beta,
    float* __restrict__ hout)
{
    int warp = blockIdx.x * 8 + (threadIdx.x >> 5);
    int lane = threadIdx.x & 31;
    if (warp >= NN) return;
    float ws = g_wsum[warp];

    const float4* A4 = (const float4*)g_A;
    const float4* B4 = (const float4*)g_Bt;
    const float4* C4 = (const float4*)g_Cb;

    float4 acc = C4[warp * 32 + lane];
    float4 bv  = B4[warp * 32 + lane];
    acc.x -= ws * bv.x; acc.y -= ws * bv.y;
    acc.z -= ws * bv.z; acc.w -= ws * bv.w;

    int e  = g_rowstart[warp];
    int e1 = g_rowstart[warp + 1];
    // unroll by 2 for MLP
    for (; e + 1 < e1; e += 2) {
        int   s0 = g_csr_src[e],   s1 = g_csr_src[e + 1];
        float w0 = g_csr_w[e],     w1 = g_csr_w[e + 1];
        float4 a0 = A4[s0 * 32 + lane];
        float4 a1 = A4[s1 * 32 + lane];
        acc.x += w0 * a0.x + w1 * a1.x;
        acc.y += w0 * a0.y + w1 * a1.y;
        acc.z += w0 * a0.z + w1 * a1.z;
        acc.w += w0 * a0.w + w1 * a1.w;
    }
    if (e < e1) {
        int s = g_csr_src[e]; float w = g_csr_w[e];
        float4 a = A4[s * 32 + lane];
        acc.x += w * a.x; acc.y += w * a.y; acc.z += w * a.z; acc.w += w * a.w;
    }

    // LayerNorm over the 128-wide row (4 vals/lane)
    float sum = acc.x + acc.y + acc.z + acc.w;
    float sq  = acc.x * acc.x + acc.y * acc.y + acc.z * acc.z + acc.w * acc.w;
#pragma unroll
    for (int o = 16; o > 0; o >>= 1) {
        sum += __shfl_xor_sync(0xffffffffu, sum, o);
        sq  += __shfl_xor_sync(0xffffffffu, sq,  o);
    }
    float mean = sum * (1.f / 128.f);
    float var  = sq * (1.f / 128.f) - mean * mean;
    float rs   = rsqrtf(var + 1e-5f);

    float4 gv = ((const float4*)gamma)[lane];
    float4 bt = ((const float4*)beta)[lane];
    float4 o;
    o.x = (acc.x - mean) * rs * gv.x + bt.x;
    o.y = (acc.y - mean) * rs * gv.y + bt.y;
    o.z = (acc.z - mean) * rs * gv.z + bt.z;
    o.w = (acc.w - mean) * rs * gv.w + bt.w;
    // leaky relu, slope 0.1
    o.x = o.x >= 0.f ? o.x : 0.1f * o.x;
    o.y = o.y >= 0.f ? o.y : 0.1f * o.y;
    o.z = o.z >= 0.f ? o.z : 0.1f * o.z;
    o.w = o.w >= 0.f ? o.w : 0.1f * o.w;
    ((float4*)hout)[warp * 32 + lane] = o;
}

// ---------------- output layer (D_OUT = 1) ----------------------------------
__global__ void __launch_bounds__(256) final_lin_kernel(
    const float* __restrict__ H,
    const float* __restrict__ W1, const float* __restrict__ b1,
    const float* __restrict__ W2,
    const float* __restrict__ W3, const float* __restrict__ b3)
{
    int warp = blockIdx.x * 8 + (threadIdx.x >> 5);
    int lane = threadIdx.x & 31;
    if (warp >= NN) return;
    float4 h  = ((const float4*)H)[warp * 32 + lane];
    float4 w1 = ((const float4*)W1)[lane];
    float4 w2 = ((const float4*)W2)[lane];
    float4 w3 = ((const float4*)W3)[lane];
    float d1 = h.x * w1.x + h.y * w1.y + h.z * w1.z + h.w * w1.w;
    float d2 = h.x * w2.x + h.y * w2.y + h.z * w2.z + h.w * w2.w;
    float d3 = h.x * w3.x + h.y * w3.y + h.z * w3.z + h.w * w3.w;
#pragma unroll
    for (int o = 16; o > 0; o >>= 1) {
        d1 += __shfl_xor_sync(0xffffffffu, d1, o);
        d2 += __shfl_xor_sync(0xffffffffu, d2, o);
        d3 += __shfl_xor_sync(0xffffffffu, d3, o);
    }
    if (lane == 0) {
        g_A1[warp]    = d1 + b1[0];
        g_base1[warp] = (d3 + b3[0]) - g_wsum[warp] * d2;
    }
}

__global__ void __launch_bounds__(256) final_agg_kernel(float* __restrict__ out) {
    int warp = blockIdx.x * 8 + (threadIdx.x >> 5);
    int lane = threadIdx.x & 31;
    if (warp >= NN) return;
    int e0 = g_rowstart[warp], e1 = g_rowstart[warp + 1];
    float acc = 0.f;
    for (int e = e0 + lane; e < e1; e += 32)
        acc += g_csr_w[e] * g_A1[g_csr_src[e]];
#pragma unroll
    for (int o = 16; o > 0; o >>= 1)
        acc += __shfl_xor_sync(0xffffffffu, acc, o);
    if (lane == 0) {
        float z = g_base1[warp] + acc;
        out[warp] = 1.f / (1.f + expf(-z));
    }
}

// ---------------- host orchestration ----------------------------------------
extern "C" void kernel_launch(void* const* d_in, const int* in_sizes, int n_in,
                              void* d_out, int out_size) {
    (void)in_sizes; (void)n_in; (void)out_size;
    const float* x    = (const float*)d_in[0];
    const float* ew   = (const float*)d_in[1];
    const float* W1_in = (const float*)d_in[2];
    const float* b1_in = (const float*)d_in[3];
    const float* W2_in = (const float*)d_in[4];
    const float* W3_in = (const float*)d_in[5];
    const float* b3_in = (const float*)d_in[6];
    const float* W1_h  = (const float*)d_in[7];
    const float* b1_h  = (const float*)d_in[8];
    const float* W2_h  = (const float*)d_in[9];
    const float* W3_h  = (const float*)d_in[10];
    const float* b3_h  = (const float*)d_in[11];
    const float* W1_o  = (const float*)d_in[12];
    const float* b1_o  = (const float*)d_in[13];
    const float* W2_o  = (const float*)d_in[14];
    const float* W3_o  = (const float*)d_in[15];
    const float* b3_o  = (const float*)d_in[16];
    const float* g1    = (const float*)d_in[17];
    const float* beta1 = (const float*)d_in[18];
    const float* g2    = (const float*)d_in[19];
    const float* beta2 = (const float*)d_in[20];
    const int*   eidx  = (const int*)d_in[21];
    float* out = (float*)d_out;

    float *buf0, *buf1, *pA, *pB, *pC;
    cudaGetSymbolAddress((void**)&buf0, g_buf0);
    cudaGetSymbolAddress((void**)&buf1, g_buf1);
    cudaGetSymbolAddress((void**)&pA, g_A);
    cudaGetSymbolAddress((void**)&pB, g_Bt);
    cudaGetSymbolAddress((void**)&pC, g_Cb);

    const int T = 256;
    zero_kernel<<<(NN + T - 1) / T, T>>>();
    colstats_kernel<<<512, 128>>>(x);
    finalize_stats_kernel<<<1, 128>>>();
    normalize_kernel<<<(NN * 32 + T - 1) / T, T>>>(x);
    deg_wsum_kernel<<<(EE + T - 1) / T, T>>>(eidx, ew);
    scan_kernel<<<1, 1024>>>();
    fill_csr_kernel<<<(EE + T - 1) / T, T>>>(eidx, ew);

    const int GB = (NN + 127) / 128;     // gemm blocks
    const int AB = (NN + 7) / 8;         // warp-per-node blocks

    // ---- layer 1 (input weights), buf0 -> buf1
    sgemm_kernel<<<GB, 256>>>(buf0, W1_in, b1_in, pA);
    sgemm_kernel<<<GB, 256>>>(buf0, W2_in, nullptr, pB);
    sgemm_kernel<<<GB, 256>>>(buf0, W3_in, b3_in, pC);
    agg_ln_kernel<<<AB, 256>>>(g1, beta1, buf1);

    // ---- layer 2 (hidden), buf1 -> buf0
    sgemm_kernel<<<GB, 256>>>(buf1, W1_h, b1_h, pA);
    sgemm_kernel<<<GB, 256>>>(buf1, W2_h, nullptr, pB);
    sgemm_kernel<<<GB, 256>>>(buf1, W3_h, b3_h, pC);
    agg_ln_kernel<<<AB, 256>>>(g2, beta2, buf0);

    // ---- layer 3 (hidden), buf0 -> buf1
    sgemm_kernel<<<GB, 256>>>(buf0, W1_h, b1_h, pA);
    sgemm_kernel<<<GB, 256>>>(buf0, W2_h, nullptr, pB);
    sgemm_kernel<<<GB, 256>>>(buf0, W3_h, b3_h, pC);
    agg_ln_kernel<<<AB, 256>>>(g2, beta2, buf1);

    // ---- output layer (D_OUT = 1), buf1 -> out
    final_lin_kernel<<<AB, 256>>>(buf1, W1_o, b1_o, W2_o, W3_o, b3_o);
    final_agg_kernel<<<AB, 256>>>(out);
}

// round 6
// speedup vs baseline: 1.1224x; 1.1224x over previous
#include <cuda_runtime.h>
#include <math.h>
#include <stdint.h>

#define NN 50000
#define EE 600000
#define D  128
#define NTILES ((NN + 127) / 128)

// ---------------- device scratch (static: no allocation allowed) -------------
__device__ float  g_buf0[NN * D];
__device__ float  g_buf1[NN * D];
__device__ float  g_A [NN * D];   // lin1(x) (+b1)
__device__ float  g_Bt[NN * D];   // lin2(x) (no bias)
__device__ float  g_Cb[NN * D];   // lin3(x) (+b3)
__device__ float  g_wsum[NN];
__device__ int    g_deg[NN];
__device__ int    g_fill[NN];
__device__ int    g_rowstart[NN + 1];
__device__ int    g_csr_src[EE];
__device__ float  g_csr_w[EE];
__device__ double g_sumd[D];
__device__ double g_sumsqd[D];
__device__ float  g_mean[D];
__device__ float  g_invs[D];
__device__ float  g_A1[NN];
__device__ float  g_base1[NN];

// ---------------- setup kernels ---------------------------------------------
__global__ void zero_kernel() {
    int i = blockIdx.x * blockDim.x + threadIdx.x;
    if (i < D) { g_sumd[i] = 0.0; g_sumsqd[i] = 0.0; }
    if (i < NN) { g_wsum[i] = 0.f; g_deg[i] = 0; g_fill[i] = 0; }
}

__global__ void colstats_kernel(const float* __restrict__ x) {
    int c = threadIdx.x;
    double s = 0.0, sq = 0.0;
    for (int r = blockIdx.x; r < NN; r += gridDim.x) {
        float v = x[r * D + c];
        s  += (double)v;
        sq += (double)v * (double)v;
    }
    atomicAdd(&g_sumd[c], s);
    atomicAdd(&g_sumsqd[c], sq);
}

__global__ void finalize_stats_kernel() {
    int c = threadIdx.x;
    if (c >= D) return;
    double s = g_sumd[c], sq = g_sumsqd[c];
    double mean = s / (double)NN;
    double var  = (sq - s * s / (double)NN) / (double)(NN - 1);  // ddof=1
    if (var < 0.0) var = 0.0;
    g_mean[c] = (float)mean;
    g_invs[c] = (float)(1.0 / (sqrt(var) + 1e-6));
}

__global__ void normalize_kernel(const float* __restrict__ x) {
    int i = blockIdx.x * blockDim.x + threadIdx.x;
    if (i >= NN * 32) return;
    int cg = (i & 31) * 4;
    float4 v = ((const float4*)x)[i];
    v.x = (v.x - g_mean[cg + 0]) * g_invs[cg + 0];
    v.y = (v.y - g_mean[cg + 1]) * g_invs[cg + 1];
    v.z = (v.z - g_mean[cg + 2]) * g_invs[cg + 2];
    v.w = (v.w - g_mean[cg + 3]) * g_invs[cg + 3];
    ((float4*)g_buf0)[i] = v;
}

__global__ void deg_wsum_kernel(const int* __restrict__ ei, const float* __restrict__ ew) {
    int e = blockIdx.x * blockDim.x + threadIdx.x;
    if (e >= EE) return;
    int dst = ei[EE + e];
    atomicAdd(&g_wsum[dst], ew[e]);
    atomicAdd(&g_deg[dst], 1);
}

__global__ void scan_kernel() {
    __shared__ int sh[1024];
    __shared__ int carry;
    int tid = threadIdx.x;
    if (tid == 0) carry = 0;
    __syncthreads();
    for (int base = 0; base < NN; base += 1024) {
        int i = base + tid;
        int v = (i < NN) ? g_deg[i] : 0;
        sh[tid] = v;
        __syncthreads();
        for (int off = 1; off < 1024; off <<= 1) {
            int t = (tid >= off) ? sh[tid - off] : 0;
            __syncthreads();
            sh[tid] += t;
            __syncthreads();
        }
        if (i < NN) g_rowstart[i] = carry + sh[tid] - v;
        __syncthreads();
        if (tid == 1023) carry += sh[1023];
        __syncthreads();
    }
    if (tid == 0) g_rowstart[NN] = EE;
}

__global__ void fill_csr_kernel(const int* __restrict__ ei, const float* __restrict__ ew) {
    int e = blockIdx.x * blockDim.x + threadIdx.x;
    if (e >= EE) return;
    int dst = ei[EE + e];
    int p = g_rowstart[dst] + atomicAdd(&g_fill[dst], 1);
    g_csr_src[p] = ei[e];
    g_csr_w[p]   = ew[e];
}

// ---------------- fused 3-GEMM with packed fp32 FFMA2 ------------------------
// Computes outA = X@W1 (+b1), outB = X@W2, outC = X@W3 (+b3) for one 128-row
// tile per block. X tile staged once in smem (transposed); W streamed through
// a double-buffered 8x128 slice. Inner loop: fma.rn.f32x2 (2 fp32 MACs/instr).
#define GSM_XS  0
#define GSM_BS  65536
#define GSM_TOTAL (65536 + 2 * 8 * 128 * 4)

__global__ void __launch_bounds__(256, 2) gemm3_kernel(
    const float* __restrict__ X,
    const float* __restrict__ W1, const float* __restrict__ b1,
    const float* __restrict__ W2,
    const float* __restrict__ W3, const float* __restrict__ b3,
    float* __restrict__ outA, float* __restrict__ outB, float* __restrict__ outC)
{
    extern __shared__ char smem[];
    float (*Xs)[128] = (float (*)[128])(smem + GSM_XS);          // Xs[k][row]
    float (*Bs)[8][128] = (float (*)[8][128])(smem + GSM_BS);    // Bs[buf][k][col]

    int tid = threadIdx.x;
    int row0 = blockIdx.x * 128;
    int tm = (tid >> 4) * 8;
    int tn = (tid & 15) * 8;

    // ---- stage X tile, transposed: Xs[k][row] ----
    {
        int lr = tid >> 1;
        int grow = row0 + lr;
        const float4* Xr = (const float4*)(X + (size_t)grow * D);
#pragma unroll
        for (int i = 0; i < 16; ++i) {
            int col = i * 8 + (tid & 1) * 4;
            float4 v = make_float4(0.f, 0.f, 0.f, 0.f);
            if (grow < NN) v = Xr[col >> 2];
            Xs[col + 0][lr] = v.x; Xs[col + 1][lr] = v.y;
            Xs[col + 2][lr] = v.z; Xs[col + 3][lr] = v.w;
        }
    }

    int wr = tid >> 5;            // k-row within slice (0..7)
    int wc = (tid & 31) * 4;      // col (0..124)

    // preload slice 0 of W1
    *(float4*)&Bs[0][wr][wc] = *(const float4*)(W1 + wr * D + wc);

    unsigned long long acc[8][4];   // acc[i][j] = cols (tn+2j, tn+2j+1), row tm+i

    for (int s = 0; s < 48; ++s) {          // 3 mats x 16 k-slices
        int m = s >> 4;
        int t = s & 15;
        int buf = s & 1;

        __syncthreads();   // slice `buf` ready; prev reads of buf^1 done

        // prefetch next slice into buf^1
        if (s + 1 < 48) {
            int m2 = (s + 1) >> 4, t2 = (s + 1) & 15;
            const float* Wn = (m2 == 0) ? W1 : (m2 == 1) ? W2 : W3;
            *(float4*)&Bs[buf ^ 1][wr][wc] =
                *(const float4*)(Wn + (t2 * 8 + wr) * D + wc);
        }

        if (t == 0) {
#pragma unroll
            for (int i = 0; i < 8; ++i)
#pragma unroll
                for (int j = 0; j < 4; ++j) acc[i][j] = 0ull;
        }

#pragma unroll
        for (int kk = 0; kk < 8; ++kk) {
            int k = t * 8 + kk;
            float ra[8];
            *(float4*)&ra[0] = *(const float4*)&Xs[k][tm];
            *(float4*)&ra[4] = *(const float4*)&Xs[k][tm + 4];
            float4 bA = *(const float4*)&Bs[buf][kk][tn];
            float4 bB = *(const float4*)&Bs[buf][kk][tn + 4];
            unsigned long long b64[4];
            b64[0] = ((const unsigned long long*)&bA)[0];
            b64[1] = ((const unsigned long long*)&bA)[1];
            b64[2] = ((const unsigned long long*)&bB)[0];
            b64[3] = ((const unsigned long long*)&bB)[1];
#pragma unroll
            for (int i = 0; i < 8; ++i) {
                unsigned long long a2;
                asm("mov.b64 %0, {%1, %1};"
                    : "=l"(a2) : "r"(__float_as_uint(ra[i])));
#pragma unroll
                for (int j = 0; j < 4; ++j)
                    asm("fma.rn.f32x2 %0, %1, %2, %3;"
                        : "=l"(acc[i][j])
                        : "l"(a2), "l"(b64[j]), "l"(acc[i][j]));
            }
        }

        if (t == 15) {   // epilogue for mat m
            float* dst = (m == 0) ? outA : (m == 1) ? outB : outC;
            const float* bias = (m == 0) ? b1 : (m == 2) ? b3 : nullptr;
            float bv[8];
#pragma unroll
            for (int j = 0; j < 8; ++j) bv[j] = bias ? bias[tn + j] : 0.f;
#pragma unroll
            for (int i = 0; i < 8; ++i) {
                int grow = row0 + tm + i;
                if (grow < NN) {
                    float4 o0, o1;
                    o0.x = __uint_as_float((uint32_t)acc[i][0]) + bv[0];
                    o0.y = __uint_as_float((uint32_t)(acc[i][0] >> 32)) + bv[1];
                    o0.z = __uint_as_float((uint32_t)acc[i][1]) + bv[2];
                    o0.w = __uint_as_float((uint32_t)(acc[i][1] >> 32)) + bv[3];
                    o1.x = __uint_as_float((uint32_t)acc[i][2]) + bv[4];
                    o1.y = __uint_as_float((uint32_t)(acc[i][2] >> 32)) + bv[5];
                    o1.z = __uint_as_float((uint32_t)acc[i][3]) + bv[6];
                    o1.w = __uint_as_float((uint32_t)(acc[i][3] >> 32)) + bv[7];
                    float4* dp = (float4*)(dst + (size_t)grow * D + tn);
                    dp[0] = o0;
                    dp[1] = o1;
                }
            }
        }
    }
}

// ---------------- per-node aggregation + LEConv epilogue + LN + leaky -------
__global__ void __launch_bounds__(256) agg_ln_kernel(
    const float* __restrict__ gamma, const float* __restrict__ beta,
    float* __restrict__ hout)
{
    int warp = blockIdx.x * 8 + (threadIdx.x >> 5);
    int lane = threadIdx.x & 31;
    if (warp >= NN) return;
    float ws = g_wsum[warp];

    const float4* A4 = (const float4*)g_A;
    const float4* B4 = (const float4*)g_Bt;
    const float4* C4 = (const float4*)g_Cb;

    float4 acc = C4[warp * 32 + lane];
    float4 bv  = B4[warp * 32 + lane];
    acc.x -= ws * bv.x; acc.y -= ws * bv.y;
    acc.z -= ws * bv.z; acc.w -= ws * bv.w;

    int e  = g_rowstart[warp];
    int e1 = g_rowstart[warp + 1];
    for (; e + 1 < e1; e += 2) {
        int   s0 = g_csr_src[e],   s1 = g_csr_src[e + 1];
        float w0 = g_csr_w[e],     w1 = g_csr_w[e + 1];
        float4 a0 = A4[s0 * 32 + lane];
        float4 a1 = A4[s1 * 32 + lane];
        acc.x += w0 * a0.x + w1 * a1.x;
        acc.y += w0 * a0.y + w1 * a1.y;
        acc.z += w0 * a0.z + w1 * a1.z;
        acc.w += w0 * a0.w + w1 * a1.w;
    }
    if (e < e1) {
        int s = g_csr_src[e]; float w = g_csr_w[e];
        float4 a = A4[s * 32 + lane];
        acc.x += w * a.x; acc.y += w * a.y; acc.z += w * a.z; acc.w += w * a.w;
    }

    float sum = acc.x + acc.y + acc.z + acc.w;
    float sq  = acc.x * acc.x + acc.y * acc.y + acc.z * acc.z + acc.w * acc.w;
#pragma unroll
    for (int o = 16; o > 0; o >>= 1) {
        sum += __shfl_xor_sync(0xffffffffu, sum, o);
        sq  += __shfl_xor_sync(0xffffffffu, sq,  o);
    }
    float mean = sum * (1.f / 128.f);
    float var  = sq * (1.f / 128.f) - mean * mean;
    float rs   = rsqrtf(var + 1e-5f);

    float4 gv = ((const float4*)gamma)[lane];
    float4 bt = ((const float4*)beta)[lane];
    float4 o;
    o.x = (acc.x - mean) * rs * gv.x + bt.x;
    o.y = (acc.y - mean) * rs * gv.y + bt.y;
    o.z = (acc.z - mean) * rs * gv.z + bt.z;
    o.w = (acc.w - mean) * rs * gv.w + bt.w;
    o.x = o.x >= 0.f ? o.x : 0.1f * o.x;
    o.y = o.y >= 0.f ? o.y : 0.1f * o.y;
    o.z = o.z >= 0.f ? o.z : 0.1f * o.z;
    o.w = o.w >= 0.f ? o.w : 0.1f * o.w;
    ((float4*)hout)[warp * 32 + lane] = o;
}

// ---------------- output layer (D_OUT = 1) ----------------------------------
__global__ void __launch_bounds__(256) final_lin_kernel(
    const float* __restrict__ H,
    const float* __restrict__ W1, const float* __restrict__ b1,
    const float* __restrict__ W2,
    const float* __restrict__ W3, const float* __restrict__ b3)
{
    int warp = blockIdx.x * 8 + (threadIdx.x >> 5);
    int lane = threadIdx.x & 31;
    if (warp >= NN) return;
    float4 h  = ((const float4*)H)[warp * 32 + lane];
    float4 w1 = ((const float4*)W1)[lane];
    float4 w2 = ((const float4*)W2)[lane];
    float4 w3 = ((const float4*)W3)[lane];
    float d1 = h.x * w1.x + h.y * w1.y + h.z * w1.z + h.w * w1.w;
    float d2 = h.x * w2.x + h.y * w2.y + h.z * w2.z + h.w * w2.w;
    float d3 = h.x * w3.x + h.y * w3.y + h.z * w3.z + h.w * w3.w;
#pragma unroll
    for (int o = 16; o > 0; o >>= 1) {
        d1 += __shfl_xor_sync(0xffffffffu, d1, o);
        d2 += __shfl_xor_sync(0xffffffffu, d2, o);
        d3 += __shfl_xor_sync(0xffffffffu, d3, o);
    }
    if (lane == 0) {
        g_A1[warp]    = d1 + b1[0];
        g_base1[warp] = (d3 + b3[0]) - g_wsum[warp] * d2;
    }
}

__global__ void __launch_bounds__(256) final_agg_kernel(float* __restrict__ out) {
    int warp = blockIdx.x * 8 + (threadIdx.x >> 5);
    int lane = threadIdx.x & 31;
    if (warp >= NN) return;
    int e0 = g_rowstart[warp], e1 = g_rowstart[warp + 1];
    float acc = 0.f;
    for (int e = e0 + lane; e < e1; e += 32)
        acc += g_csr_w[e] * g_A1[g_csr_src[e]];
#pragma unroll
    for (int o = 16; o > 0; o >>= 1)
        acc += __shfl_xor_sync(0xffffffffu, acc, o);
    if (lane == 0) {
        float z = g_base1[warp] + acc;
        out[warp] = 1.f / (1.f + expf(-z));
    }
}

// ---------------- host orchestration ----------------------------------------
extern "C" void kernel_launch(void* const* d_in, const int* in_sizes, int n_in,
                              void* d_out, int out_size) {
    (void)in_sizes; (void)n_in; (void)out_size;
    const float* x     = (const float*)d_in[0];
    const float* ew    = (const float*)d_in[1];
    const float* W1_in = (const float*)d_in[2];
    const float* b1_in = (const float*)d_in[3];
    const float* W2_in = (const float*)d_in[4];
    const float* W3_in = (const float*)d_in[5];
    const float* b3_in = (const float*)d_in[6];
    const float* W1_h  = (const float*)d_in[7];
    const float* b1_h  = (const float*)d_in[8];
    const float* W2_h  = (const float*)d_in[9];
    const float* W3_h  = (const float*)d_in[10];
    const float* b3_h  = (const float*)d_in[11];
    const float* W1_o  = (const float*)d_in[12];
    const float* b1_o  = (const float*)d_in[13];
    const float* W2_o  = (const float*)d_in[14];
    const float* W3_o  = (const float*)d_in[15];
    const float* b3_o  = (const float*)d_in[16];
    const float* g1    = (const float*)d_in[17];
    const float* beta1 = (const float*)d_in[18];
    const float* g2    = (const float*)d_in[19];
    const float* beta2 = (const float*)d_in[20];
    const int*   eidx  = (const int*)d_in[21];
    float* out = (float*)d_out;

    float *buf0, *buf1, *pA, *pB, *pC;
    cudaGetSymbolAddress((void**)&buf0, g_buf0);
    cudaGetSymbolAddress((void**)&buf1, g_buf1);
    cudaGetSymbolAddress((void**)&pA, g_A);
    cudaGetSymbolAddress((void**)&pB, g_Bt);
    cudaGetSymbolAddress((void**)&pC, g_Cb);

    cudaFuncSetAttribute(gemm3_kernel,
                         cudaFuncAttributeMaxDynamicSharedMemorySize, GSM_TOTAL);

    const int T = 256;
    zero_kernel<<<(NN + T - 1) / T, T>>>();
    colstats_kernel<<<512, 128>>>(x);
    finalize_stats_kernel<<<1, 128>>>();
    normalize_kernel<<<(NN * 32 + T - 1) / T, T>>>(x);
    deg_wsum_kernel<<<(EE + T - 1) / T, T>>>(eidx, ew);
    scan_kernel<<<1, 1024>>>();
    fill_csr_kernel<<<(EE + T - 1) / T, T>>>(eidx, ew);

    const int AB = (NN + 7) / 8;

    // ---- layer 1 (input weights), buf0 -> buf1
    gemm3_kernel<<<NTILES, 256, GSM_TOTAL>>>(buf0, W1_in, b1_in, W2_in, W3_in, b3_in,
                                             pA, pB, pC);
    agg_ln_kernel<<<AB, 256>>>(g1, beta1, buf1);

    // ---- layer 2 (hidden), buf1 -> buf0
    gemm3_kernel<<<NTILES, 256, GSM_TOTAL>>>(buf1, W1_h, b1_h, W2_h, W3_h, b3_h,
                                             pA, pB, pC);
    agg_ln_kernel<<<AB, 256>>>(g2, beta2, buf0);

    // ---- layer 3 (hidden), buf0 -> buf1
    gemm3_kernel<<<NTILES, 256, GSM_TOTAL>>>(buf0, W1_h, b1_h, W2_h, W3_h, b3_h,
                                             pA, pB, pC);
    agg_ln_kernel<<<AB, 256>>>(g2, beta2, buf1);

    // ---- output layer (D_OUT = 1), buf1 -> out
    final_lin_kernel<<<AB, 256>>>(buf1, W1_o, b1_o, W2_o, W3_o, b3_o);
    final_agg_kernel<<<AB, 256>>>(out);
}